// round 10
// baseline (speedup 1.0000x reference)
#include <cuda_runtime.h>
#include <cuda_fp16.h>
#include <cstdint>

#define EE 256
#define HH 128
#define G4 512
#define BB 128
#define SS 1024
#define MM (SS*BB)
#define NEGV -10000.0f

__device__ float  g_G[(size_t)2*MM*G4];
__device__ __half g_xh[(size_t)MM*256];
__device__ __half g_y1h[(size_t)MM*256];
__device__ __half g_y2h[(size_t)MM*256];
__device__ __half g_wh[(size_t)2*1024*256];
__device__ float  g_bs[2*1024];
__device__ float  g_feats[(size_t)BB*SS*8];

__device__ __forceinline__ unsigned h2u(float a, float b){
    __half2 h = __floats2half2_rn(a, b);
    return *(unsigned*)&h;
}
__device__ __forceinline__ void mma16816(float* c, const unsigned* a,
                                         unsigned b0, unsigned b1){
    asm volatile("mma.sync.aligned.m16n8k16.row.col.f32.f16.f16.f32 "
        "{%0,%1,%2,%3}, {%4,%5,%6,%7}, {%8,%9}, {%0,%1,%2,%3};"
        : "+f"(c[0]), "+f"(c[1]), "+f"(c[2]), "+f"(c[3])
        : "r"(a[0]), "r"(a[1]), "r"(a[2]), "r"(a[3]), "r"(b0), "r"(b1));
}
__device__ __forceinline__ void ldm4(unsigned* r, unsigned addr){
    asm volatile("ldmatrix.sync.aligned.m8n8.x4.shared.b16 {%0,%1,%2,%3}, [%4];"
        : "=r"(r[0]), "=r"(r[1]), "=r"(r[2]), "=r"(r[3]) : "r"(addr));
}
__device__ __forceinline__ void cpa16(unsigned s, const void* g){
    asm volatile("cp.async.cg.shared.global [%0], [%1], 16;" :: "r"(s), "l"(g));
}
__device__ __forceinline__ float sigf(float x){
    return __fdividef(1.0f, 1.0f + __expf(-x));
}
__device__ __forceinline__ float tanhfast(float x){
    return __fdividef(2.0f, 1.0f + __expf(-2.0f * x)) - 1.0f;
}

// ---- prep ----
__global__ __launch_bounds__(256) void prep_x(
    const int* __restrict__ sent, const float* __restrict__ emb,
    __half* __restrict__ Xh)
{
    size_t i = (size_t)blockIdx.x * 256 + threadIdx.x;
    int m = (int)(i >> 5);
    int c = ((int)i & 31) * 8;
    const float* src = emb + (size_t)sent[m]*256 + c;
    float4 v0 = *(const float4*)src;
    float4 v1 = *(const float4*)(src + 4);
    __half2* dst = (__half2*)(Xh + (size_t)m*256 + c);
    dst[0] = __floats2half2_rn(v0.x, v0.y);
    dst[1] = __floats2half2_rn(v0.z, v0.w);
    dst[2] = __floats2half2_rn(v1.x, v1.y);
    dst[3] = __floats2half2_rn(v1.z, v1.w);
}
__global__ __launch_bounds__(256) void prep_w(
    const float* __restrict__ wih, const float* __restrict__ bih,
    const float* __restrict__ bhh, __half* __restrict__ Wh, float* __restrict__ bs)
{
    size_t i = (size_t)blockIdx.x * 256 + threadIdx.x;
    Wh[i] = __float2half(wih[i]);
    if (i < 2048) bs[i] = bih[i] + bhh[i];
}

// ---- HMMA GEMM, cp.async double-buffered K pipeline, 2 blocks/SM ----
// 128x128 tile, K = 4 chunks of 64. smem/stage: X[128][72] + W[128][72] halfs.
#define KC 64
#define ST2 72
#define XCH (128*ST2)                 // halfs per X (or W) chunk
#define STAGEH (2*XCH)                // halfs per stage
__global__ __launch_bounds__(256, 2) void gemm16(
    const __half* __restrict__ Xh, const __half* __restrict__ Wh,
    const float* __restrict__ bs, float* __restrict__ G)
{
    extern __shared__ __half sm[];
    const int tid = threadIdx.x;
    const int n0 = blockIdx.x * 128;
    const int m0 = blockIdx.y * 128;

    unsigned sbase = (unsigned)__cvta_generic_to_shared(sm);
    const int lrow = tid >> 3, lc16 = tid & 7;   // 32 rows x 8 16B-lines per 256-thr pass

    // load chunk kc into stage stg (4 passes cover 128 rows)
#define LOAD_STAGE(kc, stg) do{                                              \
        unsigned xb = sbase + (unsigned)(stg)*STAGEH*2;                      \
        unsigned wb = xb + XCH*2;                                            \
        _Pragma("unroll")                                                    \
        for (int it = 0; it < 4; it++){                                      \
            int row = lrow + 32*it;                                          \
            unsigned off = (unsigned)(row*ST2 + lc16*8)*2;                   \
            cpa16(xb + off, Xh + (size_t)(m0+row)*256 + (kc)*KC + lc16*8);   \
            cpa16(wb + off, Wh + (size_t)(n0+row)*256 + (kc)*KC + lc16*8);   \
        }                                                                    \
        asm volatile("cp.async.commit_group;");                              \
    }while(0)

    LOAD_STAGE(0, 0);
    LOAD_STAGE(1, 1);

    const int w = tid >> 5, lane = tid & 31;
    const int wm = (w >> 1) * 32, wn = (w & 1) * 64;
    float acc[2][8][4];
#pragma unroll
    for (int i=0;i<2;i++) for (int j=0;j<8;j++) for (int k=0;k<4;k++) acc[i][j][k]=0.f;

#pragma unroll
    for (int ch = 0; ch < 4; ch++){
        if (ch < 3) asm volatile("cp.async.wait_group 1;");
        else        asm volatile("cp.async.wait_group 0;");
        __syncthreads();

        unsigned xb = sbase + (unsigned)(ch & 1)*STAGEH*2;
        unsigned wb = xb + XCH*2;
#pragma unroll
        for (int kt = 0; kt < 4; kt++){
            unsigned a[2][4], b[4][4];
#pragma unroll
            for (int mt = 0; mt < 2; mt++){
                int row = wm + mt*16 + (lane & 15);
                int k = kt*16 + (lane >> 4)*8;
                ldm4(a[mt], xb + (unsigned)(row*ST2 + k)*2);
            }
#pragma unroll
            for (int nh = 0; nh < 4; nh++){
                int row = wn + nh*16 + ((lane>>4)&1)*8 + (lane & 7);
                int k = kt*16 + ((lane>>3)&1)*8;
                ldm4(b[nh], wb + (unsigned)(row*ST2 + k)*2);
            }
#pragma unroll
            for (int mt = 0; mt < 2; mt++)
#pragma unroll
                for (int nh = 0; nh < 4; nh++){
                    mma16816(acc[mt][nh*2],   a[mt], b[nh][0], b[nh][1]);
                    mma16816(acc[mt][nh*2+1], a[mt], b[nh][2], b[nh][3]);
                }
        }
        __syncthreads();
        if (ch + 2 < 4) LOAD_STAGE(ch + 2, ch & 1);
    }

    const int d = n0 >> 9;
    const int t = m0 >> 7;
#pragma unroll
    for (int mt = 0; mt < 2; mt++){
#pragma unroll
        for (int nt = 0; nt < 8; nt++){
            int g = n0 + wn + nt*8 + (lane & 3)*2;
            float b0 = bs[g], b1 = bs[g+1];
            int gl = g & 511;
            int bA = (m0 + wm + mt*16 + (lane>>2)) & 127;
            size_t o = ((size_t)d*MM + (size_t)t*128)*512 + gl;
            *(float2*)(G + o + (size_t)bA*512) =
                make_float2(acc[mt][nt][0]+b0, acc[mt][nt][1]+b1);
            *(float2*)(G + o + (size_t)(bA+8)*512) =
                make_float2(acc[mt][nt][2]+b0, acc[mt][nt][3]+b1);
        }
    }
}

// ---- LSTM recurrence: block = (4-batch group, dir), 64 blocks.
// Gate-permuted A fragments, lane-local activation, double-buffered h,
// one barrier/step, 4 independent mma accumulator chains. ----
__global__ __launch_bounds__(512, 1) void lstm_layer(
    const float* __restrict__ G, const float* __restrict__ whhL,
    const float* __restrict__ h0L, const float* __restrict__ c0L,
    __half* __restrict__ Yh)
{
    __shared__ __half hs[2][8][136];

    const int tid = threadIdx.x;
    const int w = tid >> 5, lane = tid & 31;
    const int d = blockIdx.y;
    const int b0 = blockIdx.x * 4;

    const float* wr = whhL + (size_t)d*G4*HH;
    unsigned wa[2][8][4];
#pragma unroll
    for (int mt = 0; mt < 2; mt++)
#pragma unroll
        for (int kt = 0; kt < 8; kt++)
#pragma unroll
            for (int r = 0; r < 4; r++){
                int grow = mt*16 + (lane>>2) + 8*(r & 1);
                int row = (grow >> 3)*128 + w*8 + (grow & 7);
                int k = kt*16 + (lane&3)*2 + 8*(r >> 1);
                wa[mt][kt][r] = h2u(wr[(size_t)row*HH + k], wr[(size_t)row*HH + k + 1]);
            }

    for (int i = tid; i < 2*8*136; i += 512) (&hs[0][0][0])[i] = __float2half(0.f);
    __syncthreads();

    const int q = lane >> 2, c = lane & 3;
    const int cell = w*8 + q;
    const size_t hb = (size_t)d*(BB*HH);
    float cv = c0L[hb + (size_t)(b0+c)*HH + cell];
    hs[0][2*c][cell] = __float2half(h0L[hb + (size_t)(b0+c)*HH + cell]);
    __syncthreads();

    const float* gbase = G + ((size_t)d*MM + b0 + c)*512 + cell;
    int tf = d ? (SS-1) : 0;
    float gp[4];
#pragma unroll
    for (int k = 0; k < 4; k++)
        gp[k] = gbase[(size_t)tf*BB*512 + 128*k];

    unsigned hsb0 = (unsigned)__cvta_generic_to_shared(&hs[0][0][0]);
    const unsigned boff = ((lane>>2)*136 + (lane&3)*2)*2;

    __half hprev = __float2half(0.f);
    size_t yprev = 0;
    bool havePrev = false;

    for (int s = 0; s < SS; s++){
        const int t = d ? (SS-1-s) : s;
        const int p = s & 1;
        unsigned hsb = hsb0 + (unsigned)(p * 8*136*2);

        // 4 independent accumulator chains (kt parity x mt)
        float acc[4][4];
#pragma unroll
        for (int i=0;i<4;i++) for (int z=0;z<4;z++) acc[i][z]=0.f;
#pragma unroll
        for (int kt = 0; kt < 8; kt++){
            unsigned off = hsb + boff + kt*32;
            unsigned bf0, bf1;
            asm volatile("ld.shared.b32 %0, [%1];" : "=r"(bf0) : "r"(off));
            asm volatile("ld.shared.b32 %0, [%1];" : "=r"(bf1) : "r"(off + 16));
            int e = (kt & 1) * 2;
            mma16816(acc[e],   wa[0][kt], bf0, bf1);
            mma16816(acc[e+1], wa[1][kt], bf0, bf1);
        }

        float gi = acc[0][0] + acc[2][0] + gp[0];
        float gf = acc[0][2] + acc[2][2] + gp[1];
        float gg = acc[1][0] + acc[3][0] + gp[2];
        float go = acc[1][2] + acc[3][2] + gp[3];

        if (s < SS-1){
            int tn = d ? (SS-2-s) : (s+1);
            size_t o = (size_t)tn*BB*512;
#pragma unroll
            for (int k = 0; k < 4; k++) gp[k] = gbase[o + 128*k];
        }

        float ig = sigf(gi), fg = sigf(gf);
        float g2 = tanhfast(gg), og = sigf(go);
        cv = fg*cv + ig*g2;
        float h = og * tanhfast(cv);
        __half h16 = __float2half(h);

        hs[1-p][2*c][cell] = h16;
        __syncthreads();
        // Y store after the barrier (off the arrival critical path)
        if (havePrev) Yh[yprev] = hprev;
        hprev = h16;
        yprev = ((size_t)t*BB + b0 + c)*256 + d*128 + cell;
        havePrev = true;
    }
    Yh[yprev] = hprev;
}

// ---- feats ----
__global__ __launch_bounds__(256) void feats_kernel(
    const __half* __restrict__ Y2, const float* __restrict__ wout,
    const float* __restrict__ bout, float* __restrict__ F)
{
    __shared__ float W[7][256];
    __shared__ float bo[7];
    const int tid = threadIdx.x;
    for (int i = tid; i < 7*256; i += 256) W[i>>8][i&255] = wout[i];
    if (tid < 7) bo[tid] = bout[tid];
    __syncthreads();
    const int warp = tid >> 5, lane = tid & 31;
    const size_t m = (size_t)blockIdx.x * 8 + warp;
    const __half* yr = Y2 + m * 256;
    float acc[7] = {0,0,0,0,0,0,0};
#pragma unroll
    for (int i = 0; i < 8; i++){
        int k = lane + 32*i;
        float x = __half2float(yr[k]);
#pragma unroll
        for (int t = 0; t < 7; t++) acc[t] += x * W[t][k];
    }
#pragma unroll
    for (int t = 0; t < 7; t++)
        for (int off = 16; off; off >>= 1)
            acc[t] += __shfl_down_sync(0xffffffffu, acc[t], off);
    if (lane == 0){
        int s = (int)(m >> 7), b = (int)(m & 127);
        float* fo = F + ((size_t)b*SS + s)*8;
#pragma unroll
        for (int t = 0; t < 7; t++) fo[t] = acc[t] + bo[t];
    }
}

// ---- Viterbi ----
__global__ __launch_bounds__(32) void viterbi_kernel(
    const float* __restrict__ F, const float* __restrict__ trans,
    float* __restrict__ out)
{
    __shared__ unsigned char bp[SS*8];
    const int b = blockIdx.x, lane = threadIdx.x;
    float tr[7];
#pragma unroll
    for (int p = 0; p < 7; p++) tr[p] = (lane < 7) ? trans[lane*7 + p] : 0.f;
    float fv = (lane == 5) ? 0.f : NEGV;
    const float* fb = F + (size_t)b*SS*8;
    for (int s = 0; s < SS; s++){
        float m = -3.4e38f; int arg = 0;
#pragma unroll
        for (int p = 0; p < 7; p++){
            float v = __shfl_sync(0xffffffffu, fv, p) + tr[p];
            if (v > m){ m = v; arg = p; }
        }
        if (lane < 7){
            fv = m + fb[s*8 + lane];
            bp[s*8 + lane] = (unsigned char)arg;
        }
    }
    __syncwarp();
    float term = fv + ((lane < 7) ? trans[6*7 + lane] : 0.f);
    if (lane >= 7) term = -3.4e38f;
    float bestv = -3.4e38f; int best = 0;
#pragma unroll
    for (int n = 0; n < 7; n++){
        float v = __shfl_sync(0xffffffffu, term, n);
        if (v > bestv){ bestv = v; best = n; }
    }
    if (lane == 0){
        out[(size_t)BB*SS + b] = bestv;
        float* po = out + (size_t)b*SS;
        int tag = best;
        for (int s = SS-1; s > 0; --s){ po[s] = (float)tag; tag = bp[s*8 + tag]; }
        po[0] = (float)tag;
    }
}

extern "C" void kernel_launch(void* const* d_in, const int* in_sizes, int n_in,
                              void* d_out, int out_size)
{
    const int*   sentence = (const int*)  d_in[0];
    const float* embed    = (const float*)d_in[1];
    const float* w_ih     = (const float*)d_in[2];
    const float* w_hh     = (const float*)d_in[3];
    const float* b_ih     = (const float*)d_in[4];
    const float* b_hh     = (const float*)d_in[5];
    const float* h0       = (const float*)d_in[6];
    const float* c0       = (const float*)d_in[7];
    const float* w_out    = (const float*)d_in[8];
    const float* b_out    = (const float*)d_in[9];
    const float* trans    = (const float*)d_in[10];
    float* out = (float*)d_out;

    float *G, *F, *BS;
    __half *Xh, *Y1h, *Y2h, *Wh;
    cudaGetSymbolAddress((void**)&G,   g_G);
    cudaGetSymbolAddress((void**)&F,   g_feats);
    cudaGetSymbolAddress((void**)&BS,  g_bs);
    cudaGetSymbolAddress((void**)&Xh,  g_xh);
    cudaGetSymbolAddress((void**)&Y1h, g_y1h);
    cudaGetSymbolAddress((void**)&Y2h, g_y2h);
    cudaGetSymbolAddress((void**)&Wh,  g_wh);

    const int gsmem = 2 * STAGEH * 2;   // 2 stages * (X+W chunk) halfs * 2B = 73728
    cudaFuncSetAttribute(gemm16, cudaFuncAttributeMaxDynamicSharedMemorySize, gsmem);

    prep_x<<<MM*32/256, 256>>>(sentence, embed, Xh);
    prep_w<<<2048, 256>>>(w_ih, b_ih, b_hh, Wh, BS);

    dim3 ggrid(8, 1024);
    dim3 lgrid(32, 2);

    gemm16<<<ggrid, 256, gsmem>>>(Xh, Wh, BS, G);
    lstm_layer<<<lgrid, 512>>>(G, w_hh, h0, c0, Y1h);

    gemm16<<<ggrid, 256, gsmem>>>(Y1h, Wh + (size_t)1024*256, BS + 1024, G);
    lstm_layer<<<lgrid, 512>>>(G, w_hh + (size_t)1024*HH,
                               h0 + (size_t)2*BB*HH, c0 + (size_t)2*BB*HH, Y2h);

    feats_kernel<<<MM/8, 256>>>(Y2h, w_out, b_out, F);
    viterbi_kernel<<<BB, 32>>>(F, trans, out);
}

// round 11
// speedup vs baseline: 1.0072x; 1.0072x over previous
#include <cuda_runtime.h>
#include <cuda_fp16.h>
#include <cstdint>

#define EE 256
#define HH 128
#define G4 512
#define BB 128
#define SS 1024
#define MM (SS*BB)
#define NEGV -10000.0f

__device__ __half g_G[(size_t)2*MM*G4];     // fp16 gate preacts (268MB)
__device__ __half g_xh[(size_t)MM*256];
__device__ __half g_y1h[(size_t)MM*256];
__device__ __half g_y2h[(size_t)MM*256];
__device__ __half g_wh[(size_t)2*1024*256];
__device__ float  g_bs[2*1024];
__device__ float  g_feats[(size_t)BB*SS*8];

__device__ __forceinline__ unsigned h2u(float a, float b){
    __half2 h = __floats2half2_rn(a, b);
    return *(unsigned*)&h;
}
__device__ __forceinline__ void mma16816(float* c, const unsigned* a,
                                         unsigned b0, unsigned b1){
    asm volatile("mma.sync.aligned.m16n8k16.row.col.f32.f16.f16.f32 "
        "{%0,%1,%2,%3}, {%4,%5,%6,%7}, {%8,%9}, {%0,%1,%2,%3};"
        : "+f"(c[0]), "+f"(c[1]), "+f"(c[2]), "+f"(c[3])
        : "r"(a[0]), "r"(a[1]), "r"(a[2]), "r"(a[3]), "r"(b0), "r"(b1));
}
__device__ __forceinline__ void ldm4(unsigned* r, unsigned addr){
    asm volatile("ldmatrix.sync.aligned.m8n8.x4.shared.b16 {%0,%1,%2,%3}, [%4];"
        : "=r"(r[0]), "=r"(r[1]), "=r"(r[2]), "=r"(r[3]) : "r"(addr));
}
__device__ __forceinline__ void cpa16(unsigned s, const void* g){
    asm volatile("cp.async.cg.shared.global [%0], [%1], 16;" :: "r"(s), "l"(g));
}
__device__ __forceinline__ float sigf(float x){
    return __fdividef(1.0f, 1.0f + __expf(-x));
}
__device__ __forceinline__ float tanhfast(float x){
    return __fdividef(2.0f, 1.0f + __expf(-2.0f * x)) - 1.0f;
}

// ---- prep ----
__global__ __launch_bounds__(256) void prep_x(
    const int* __restrict__ sent, const float* __restrict__ emb,
    __half* __restrict__ Xh)
{
    size_t i = (size_t)blockIdx.x * 256 + threadIdx.x;
    int m = (int)(i >> 5);
    int c = ((int)i & 31) * 8;
    const float* src = emb + (size_t)sent[m]*256 + c;
    float4 v0 = *(const float4*)src;
    float4 v1 = *(const float4*)(src + 4);
    __half2* dst = (__half2*)(Xh + (size_t)m*256 + c);
    dst[0] = __floats2half2_rn(v0.x, v0.y);
    dst[1] = __floats2half2_rn(v0.z, v0.w);
    dst[2] = __floats2half2_rn(v1.x, v1.y);
    dst[3] = __floats2half2_rn(v1.z, v1.w);
}
__global__ __launch_bounds__(256) void prep_w(
    const float* __restrict__ wih, const float* __restrict__ bih,
    const float* __restrict__ bhh, __half* __restrict__ Wh, float* __restrict__ bs)
{
    size_t i = (size_t)blockIdx.x * 256 + threadIdx.x;
    Wh[i] = __float2half(wih[i]);
    if (i < 2048) bs[i] = bih[i] + bhh[i];
}

// ---- HMMA GEMM, cp.async double-buffered K pipeline, 2 blocks/SM ----
#define KC 64
#define ST2 72
#define XCH (128*ST2)
#define STAGEH (2*XCH)
__global__ __launch_bounds__(256, 2) void gemm16(
    const __half* __restrict__ Xh, const __half* __restrict__ Wh,
    const float* __restrict__ bs, __half* __restrict__ G)
{
    extern __shared__ __half sm[];
    const int tid = threadIdx.x;
    const int n0 = blockIdx.x * 128;
    const int m0 = blockIdx.y * 128;

    unsigned sbase = (unsigned)__cvta_generic_to_shared(sm);
    const int lrow = tid >> 3, lc16 = tid & 7;

#define LOAD_STAGE(kc, stg) do{                                              \
        unsigned xb = sbase + (unsigned)(stg)*STAGEH*2;                      \
        unsigned wb = xb + XCH*2;                                            \
        _Pragma("unroll")                                                    \
        for (int it = 0; it < 4; it++){                                      \
            int row = lrow + 32*it;                                          \
            unsigned off = (unsigned)(row*ST2 + lc16*8)*2;                   \
            cpa16(xb + off, Xh + (size_t)(m0+row)*256 + (kc)*KC + lc16*8);   \
            cpa16(wb + off, Wh + (size_t)(n0+row)*256 + (kc)*KC + lc16*8);   \
        }                                                                    \
        asm volatile("cp.async.commit_group;");                              \
    }while(0)

    LOAD_STAGE(0, 0);
    LOAD_STAGE(1, 1);

    const int w = tid >> 5, lane = tid & 31;
    const int wm = (w >> 1) * 32, wn = (w & 1) * 64;
    float acc[2][8][4];
#pragma unroll
    for (int i=0;i<2;i++) for (int j=0;j<8;j++) for (int k=0;k<4;k++) acc[i][j][k]=0.f;

#pragma unroll
    for (int ch = 0; ch < 4; ch++){
        if (ch < 3) asm volatile("cp.async.wait_group 1;");
        else        asm volatile("cp.async.wait_group 0;");
        __syncthreads();

        unsigned xb = sbase + (unsigned)(ch & 1)*STAGEH*2;
        unsigned wb = xb + XCH*2;
#pragma unroll
        for (int kt = 0; kt < 4; kt++){
            unsigned a[2][4], b[4][4];
#pragma unroll
            for (int mt = 0; mt < 2; mt++){
                int row = wm + mt*16 + (lane & 15);
                int k = kt*16 + (lane >> 4)*8;
                ldm4(a[mt], xb + (unsigned)(row*ST2 + k)*2);
            }
#pragma unroll
            for (int nh = 0; nh < 4; nh++){
                int row = wn + nh*16 + ((lane>>4)&1)*8 + (lane & 7);
                int k = kt*16 + ((lane>>3)&1)*8;
                ldm4(b[nh], wb + (unsigned)(row*ST2 + k)*2);
            }
#pragma unroll
            for (int mt = 0; mt < 2; mt++)
#pragma unroll
                for (int nh = 0; nh < 4; nh++){
                    mma16816(acc[mt][nh*2],   a[mt], b[nh][0], b[nh][1]);
                    mma16816(acc[mt][nh*2+1], a[mt], b[nh][2], b[nh][3]);
                }
        }
        __syncthreads();
        if (ch + 2 < 4) LOAD_STAGE(ch + 2, ch & 1);
    }

    const int d = n0 >> 9;
    const int t = m0 >> 7;
#pragma unroll
    for (int mt = 0; mt < 2; mt++){
#pragma unroll
        for (int nt = 0; nt < 8; nt++){
            int g = n0 + wn + nt*8 + (lane & 3)*2;
            float b0 = bs[g], b1 = bs[g+1];
            int gl = g & 511;
            int bA = (m0 + wm + mt*16 + (lane>>2)) & 127;
            size_t o = ((size_t)d*MM + (size_t)t*128)*512 + gl;
            *(__half2*)(G + o + (size_t)bA*512) =
                __floats2half2_rn(acc[mt][nt][0]+b0, acc[mt][nt][1]+b1);
            *(__half2*)(G + o + (size_t)(bA+8)*512) =
                __floats2half2_rn(acc[mt][nt][2]+b0, acc[mt][nt][3]+b1);
        }
    }
}

// ---- LSTM recurrence (R9 structure, fp16 G): block = (4-batch, dir), 64 blocks ----
__global__ __launch_bounds__(512, 1) void lstm_layer(
    const __half* __restrict__ G, const float* __restrict__ whhL,
    const float* __restrict__ h0L, const float* __restrict__ c0L,
    __half* __restrict__ Yh)
{
    __shared__ __half hs[2][8][136];

    const int tid = threadIdx.x;
    const int w = tid >> 5, lane = tid & 31;
    const int d = blockIdx.y;
    const int b0 = blockIdx.x * 4;

    const float* wr = whhL + (size_t)d*G4*HH;
    unsigned wa[2][8][4];
#pragma unroll
    for (int mt = 0; mt < 2; mt++)
#pragma unroll
        for (int kt = 0; kt < 8; kt++)
#pragma unroll
            for (int r = 0; r < 4; r++){
                int grow = mt*16 + (lane>>2) + 8*(r & 1);
                int row = (grow >> 3)*128 + w*8 + (grow & 7);
                int k = kt*16 + (lane&3)*2 + 8*(r >> 1);
                wa[mt][kt][r] = h2u(wr[(size_t)row*HH + k], wr[(size_t)row*HH + k + 1]);
            }

    for (int i = tid; i < 2*8*136; i += 512) (&hs[0][0][0])[i] = __float2half(0.f);
    __syncthreads();

    const int q = lane >> 2, c = lane & 3;
    const int cell = w*8 + q;
    const size_t hb = (size_t)d*(BB*HH);
    float cv = c0L[hb + (size_t)(b0+c)*HH + cell];
    hs[0][2*c][cell] = __float2half(h0L[hb + (size_t)(b0+c)*HH + cell]);
    __syncthreads();

    const __half* gbase = G + ((size_t)d*MM + b0 + c)*512 + cell;
    int tf = d ? (SS-1) : 0;
    float gp[4];
#pragma unroll
    for (int k = 0; k < 4; k++)
        gp[k] = __half2float(gbase[(size_t)tf*BB*512 + 128*k]);

    unsigned hsb0 = (unsigned)__cvta_generic_to_shared(&hs[0][0][0]);
    const unsigned boff = ((lane>>2)*136 + (lane&3)*2)*2;

    for (int s = 0; s < SS; s++){
        const int t = d ? (SS-1-s) : s;
        const int p = s & 1;
        unsigned hsb = hsb0 + (unsigned)(p * 8*136*2);

        float acc[2][4];
#pragma unroll
        for (int i=0;i<2;i++) for (int z=0;z<4;z++) acc[i][z]=0.f;
#pragma unroll
        for (int kt = 0; kt < 8; kt++){
            unsigned off = hsb + boff + kt*32;
            unsigned bf0, bf1;
            asm volatile("ld.shared.b32 %0, [%1];" : "=r"(bf0) : "r"(off));
            asm volatile("ld.shared.b32 %0, [%1];" : "=r"(bf1) : "r"(off + 16));
            mma16816(acc[0], wa[0][kt], bf0, bf1);
            mma16816(acc[1], wa[1][kt], bf0, bf1);
        }

        float gi = acc[0][0] + gp[0];
        float gf = acc[0][2] + gp[1];
        float gg = acc[1][0] + gp[2];
        float go = acc[1][2] + gp[3];

        if (s < SS-1){
            int tn = d ? (SS-2-s) : (s+1);
            size_t o = (size_t)tn*BB*512;
#pragma unroll
            for (int k = 0; k < 4; k++) gp[k] = __half2float(gbase[o + 128*k]);
        }

        float ig = sigf(gi), fg = sigf(gf);
        float g2 = tanhfast(gg), og = sigf(go);
        cv = fg*cv + ig*g2;
        float h = og * tanhfast(cv);

        hs[1-p][2*c][cell] = __float2half(h);
        Yh[((size_t)t*BB + b0 + c)*256 + d*128 + cell] = __float2half(h);
        __syncthreads();
    }
}

// ---- feats ----
__global__ __launch_bounds__(256) void feats_kernel(
    const __half* __restrict__ Y2, const float* __restrict__ wout,
    const float* __restrict__ bout, float* __restrict__ F)
{
    __shared__ float W[7][256];
    __shared__ float bo[7];
    const int tid = threadIdx.x;
    for (int i = tid; i < 7*256; i += 256) W[i>>8][i&255] = wout[i];
    if (tid < 7) bo[tid] = bout[tid];
    __syncthreads();
    const int warp = tid >> 5, lane = tid & 31;
    const size_t m = (size_t)blockIdx.x * 8 + warp;
    const __half* yr = Y2 + m * 256;
    float acc[7] = {0,0,0,0,0,0,0};
#pragma unroll
    for (int i = 0; i < 8; i++){
        int k = lane + 32*i;
        float x = __half2float(yr[k]);
#pragma unroll
        for (int t = 0; t < 7; t++) acc[t] += x * W[t][k];
    }
#pragma unroll
    for (int t = 0; t < 7; t++)
        for (int off = 16; off; off >>= 1)
            acc[t] += __shfl_down_sync(0xffffffffu, acc[t], off);
    if (lane == 0){
        int s = (int)(m >> 7), b = (int)(m & 127);
        float* fo = F + ((size_t)b*SS + s)*8;
#pragma unroll
        for (int t = 0; t < 7; t++) fo[t] = acc[t] + bo[t];
    }
}

// ---- Viterbi ----
__global__ __launch_bounds__(32) void viterbi_kernel(
    const float* __restrict__ F, const float* __restrict__ trans,
    float* __restrict__ out)
{
    __shared__ unsigned char bp[SS*8];
    const int b = blockIdx.x, lane = threadIdx.x;
    float tr[7];
#pragma unroll
    for (int p = 0; p < 7; p++) tr[p] = (lane < 7) ? trans[lane*7 + p] : 0.f;
    float fv = (lane == 5) ? 0.f : NEGV;
    const float* fb = F + (size_t)b*SS*8;
    for (int s = 0; s < SS; s++){
        float m = -3.4e38f; int arg = 0;
#pragma unroll
        for (int p = 0; p < 7; p++){
            float v = __shfl_sync(0xffffffffu, fv, p) + tr[p];
            if (v > m){ m = v; arg = p; }
        }
        if (lane < 7){
            fv = m + fb[s*8 + lane];
            bp[s*8 + lane] = (unsigned char)arg;
        }
    }
    __syncwarp();
    float term = fv + ((lane < 7) ? trans[6*7 + lane] : 0.f);
    if (lane >= 7) term = -3.4e38f;
    float bestv = -3.4e38f; int best = 0;
#pragma unroll
    for (int n = 0; n < 7; n++){
        float v = __shfl_sync(0xffffffffu, term, n);
        if (v > bestv){ bestv = v; best = n; }
    }
    if (lane == 0){
        out[(size_t)BB*SS + b] = bestv;
        float* po = out + (size_t)b*SS;
        int tag = best;
        for (int s = SS-1; s > 0; --s){ po[s] = (float)tag; tag = bp[s*8 + tag]; }
        po[0] = (float)tag;
    }
}

extern "C" void kernel_launch(void* const* d_in, const int* in_sizes, int n_in,
                              void* d_out, int out_size)
{
    const int*   sentence = (const int*)  d_in[0];
    const float* embed    = (const float*)d_in[1];
    const float* w_ih     = (const float*)d_in[2];
    const float* w_hh     = (const float*)d_in[3];
    const float* b_ih     = (const float*)d_in[4];
    const float* b_hh     = (const float*)d_in[5];
    const float* h0       = (const float*)d_in[6];
    const float* c0       = (const float*)d_in[7];
    const float* w_out    = (const float*)d_in[8];
    const float* b_out    = (const float*)d_in[9];
    const float* trans    = (const float*)d_in[10];
    float* out = (float*)d_out;

    float *F, *BS;
    __half *G, *Xh, *Y1h, *Y2h, *Wh;
    cudaGetSymbolAddress((void**)&G,   g_G);
    cudaGetSymbolAddress((void**)&F,   g_feats);
    cudaGetSymbolAddress((void**)&BS,  g_bs);
    cudaGetSymbolAddress((void**)&Xh,  g_xh);
    cudaGetSymbolAddress((void**)&Y1h, g_y1h);
    cudaGetSymbolAddress((void**)&Y2h, g_y2h);
    cudaGetSymbolAddress((void**)&Wh,  g_wh);

    const int gsmem = 2 * STAGEH * 2;
    cudaFuncSetAttribute(gemm16, cudaFuncAttributeMaxDynamicSharedMemorySize, gsmem);

    prep_x<<<MM*32/256, 256>>>(sentence, embed, Xh);
    prep_w<<<2048, 256>>>(w_ih, b_ih, b_hh, Wh, BS);

    dim3 ggrid(8, 1024);
    dim3 lgrid(32, 2);

    gemm16<<<ggrid, 256, gsmem>>>(Xh, Wh, BS, G);
    lstm_layer<<<lgrid, 512>>>(G, w_hh, h0, c0, Y1h);

    gemm16<<<ggrid, 256, gsmem>>>(Y1h, Wh + (size_t)1024*256, BS + 1024, G);
    lstm_layer<<<lgrid, 512>>>(G, w_hh + (size_t)1024*HH,
                               h0 + (size_t)2*BB*HH, c0 + (size_t)2*BB*HH, Y2h);

    feats_kernel<<<MM/8, 256>>>(Y2h, w_out, b_out, F);
    viterbi_kernel<<<BB, 32>>>(F, trans, out);
}

// round 12
// speedup vs baseline: 1.1536x; 1.1454x over previous
#include <cuda_runtime.h>
#include <cuda_fp16.h>
#include <cstdint>

#define EE 256
#define HH 128
#define G4 512
#define BB 128
#define SS 1024
#define MM (SS*BB)
#define NEGV -10000.0f

__device__ float  g_G[(size_t)2*MM*G4];
__device__ __half g_xh[(size_t)MM*256];
__device__ __half g_y1h[(size_t)MM*256];
__device__ __half g_y2h[(size_t)MM*256];
__device__ __half g_wh[(size_t)2*1024*256];
__device__ float  g_bs[2*1024];
__device__ float  g_feats[(size_t)BB*SS*8];

__device__ __forceinline__ unsigned h2u(float a, float b){
    __half2 h = __floats2half2_rn(a, b);
    return *(unsigned*)&h;
}
__device__ __forceinline__ void mma16816(float* c, const unsigned* a,
                                         unsigned b0, unsigned b1){
    asm volatile("mma.sync.aligned.m16n8k16.row.col.f32.f16.f16.f32 "
        "{%0,%1,%2,%3}, {%4,%5,%6,%7}, {%8,%9}, {%0,%1,%2,%3};"
        : "+f"(c[0]), "+f"(c[1]), "+f"(c[2]), "+f"(c[3])
        : "r"(a[0]), "r"(a[1]), "r"(a[2]), "r"(a[3]), "r"(b0), "r"(b1));
}
__device__ __forceinline__ void ldm4(unsigned* r, unsigned addr){
    asm volatile("ldmatrix.sync.aligned.m8n8.x4.shared.b16 {%0,%1,%2,%3}, [%4];"
        : "=r"(r[0]), "=r"(r[1]), "=r"(r[2]), "=r"(r[3]) : "r"(addr));
}
__device__ __forceinline__ void cpa16(unsigned s, const void* g){
    asm volatile("cp.async.cg.shared.global [%0], [%1], 16;" :: "r"(s), "l"(g));
}
__device__ __forceinline__ float tanha(float x){
    float y; asm("tanh.approx.f32 %0, %1;" : "=f"(y) : "f"(x)); return y;
}
__device__ __forceinline__ float sigf(float x){
    return fmaf(0.5f, tanha(0.5f * x), 0.5f);
}

// ---- prep ----
__global__ __launch_bounds__(256) void prep_x(
    const int* __restrict__ sent, const float* __restrict__ emb,
    __half* __restrict__ Xh)
{
    size_t i = (size_t)blockIdx.x * 256 + threadIdx.x;
    int m = (int)(i >> 5);
    int c = ((int)i & 31) * 8;
    const float* src = emb + (size_t)sent[m]*256 + c;
    float4 v0 = *(const float4*)src;
    float4 v1 = *(const float4*)(src + 4);
    __half2* dst = (__half2*)(Xh + (size_t)m*256 + c);
    dst[0] = __floats2half2_rn(v0.x, v0.y);
    dst[1] = __floats2half2_rn(v0.z, v0.w);
    dst[2] = __floats2half2_rn(v1.x, v1.y);
    dst[3] = __floats2half2_rn(v1.z, v1.w);
}
__global__ __launch_bounds__(256) void prep_w(
    const float* __restrict__ wih, const float* __restrict__ bih,
    const float* __restrict__ bhh, __half* __restrict__ Wh, float* __restrict__ bs)
{
    size_t i = (size_t)blockIdx.x * 256 + threadIdx.x;
    Wh[i] = __float2half(wih[i]);
    if (i < 2048) bs[i] = bih[i] + bhh[i];
}

// ---- HMMA GEMM, cp.async double-buffered K pipeline, 2 blocks/SM, fp32 out ----
#define KC 64
#define ST2 72
#define XCH (128*ST2)
#define STAGEH (2*XCH)
__global__ __launch_bounds__(256, 2) void gemm16(
    const __half* __restrict__ Xh, const __half* __restrict__ Wh,
    const float* __restrict__ bs, float* __restrict__ G)
{
    extern __shared__ __half sm[];
    const int tid = threadIdx.x;
    const int n0 = blockIdx.x * 128;
    const int m0 = blockIdx.y * 128;

    unsigned sbase = (unsigned)__cvta_generic_to_shared(sm);
    const int lrow = tid >> 3, lc16 = tid & 7;

#define LOAD_STAGE(kc, stg) do{                                              \
        unsigned xb = sbase + (unsigned)(stg)*STAGEH*2;                      \
        unsigned wb = xb + XCH*2;                                            \
        _Pragma("unroll")                                                    \
        for (int it = 0; it < 4; it++){                                      \
            int row = lrow + 32*it;                                          \
            unsigned off = (unsigned)(row*ST2 + lc16*8)*2;                   \
            cpa16(xb + off, Xh + (size_t)(m0+row)*256 + (kc)*KC + lc16*8);   \
            cpa16(wb + off, Wh + (size_t)(n0+row)*256 + (kc)*KC + lc16*8);   \
        }                                                                    \
        asm volatile("cp.async.commit_group;");                              \
    }while(0)

    LOAD_STAGE(0, 0);
    LOAD_STAGE(1, 1);

    const int w = tid >> 5, lane = tid & 31;
    const int wm = (w >> 1) * 32, wn = (w & 1) * 64;
    float acc[2][8][4];
#pragma unroll
    for (int i=0;i<2;i++) for (int j=0;j<8;j++) for (int k=0;k<4;k++) acc[i][j][k]=0.f;

#pragma unroll
    for (int ch = 0; ch < 4; ch++){
        if (ch < 3) asm volatile("cp.async.wait_group 1;");
        else        asm volatile("cp.async.wait_group 0;");
        __syncthreads();

        unsigned xb = sbase + (unsigned)(ch & 1)*STAGEH*2;
        unsigned wb = xb + XCH*2;
#pragma unroll
        for (int kt = 0; kt < 4; kt++){
            unsigned a[2][4], b[4][4];
#pragma unroll
            for (int mt = 0; mt < 2; mt++){
                int row = wm + mt*16 + (lane & 15);
                int k = kt*16 + (lane >> 4)*8;
                ldm4(a[mt], xb + (unsigned)(row*ST2 + k)*2);
            }
#pragma unroll
            for (int nh = 0; nh < 4; nh++){
                int row = wn + nh*16 + ((lane>>4)&1)*8 + (lane & 7);
                int k = kt*16 + ((lane>>3)&1)*8;
                ldm4(b[nh], wb + (unsigned)(row*ST2 + k)*2);
            }
#pragma unroll
            for (int mt = 0; mt < 2; mt++)
#pragma unroll
                for (int nh = 0; nh < 4; nh++){
                    mma16816(acc[mt][nh*2],   a[mt], b[nh][0], b[nh][1]);
                    mma16816(acc[mt][nh*2+1], a[mt], b[nh][2], b[nh][3]);
                }
        }
        __syncthreads();
        if (ch + 2 < 4) LOAD_STAGE(ch + 2, ch & 1);
    }

    const int d = n0 >> 9;
    const int t = m0 >> 7;
#pragma unroll
    for (int mt = 0; mt < 2; mt++){
#pragma unroll
        for (int nt = 0; nt < 8; nt++){
            int g = n0 + wn + nt*8 + (lane & 3)*2;
            float b0 = bs[g], b1 = bs[g+1];
            int gl = g & 511;
            int bA = (m0 + wm + mt*16 + (lane>>2)) & 127;
            size_t o = ((size_t)d*MM + (size_t)t*128)*512 + gl;
            *(float2*)(G + o + (size_t)bA*512) =
                make_float2(acc[mt][nt][0]+b0, acc[mt][nt][1]+b1);
            *(float2*)(G + o + (size_t)(bA+8)*512) =
                make_float2(acc[mt][nt][2]+b0, acc[mt][nt][3]+b1);
        }
    }
}

// ---- LSTM recurrence (R9 structure, fp32 G, tanh.approx activations) ----
__global__ __launch_bounds__(512, 1) void lstm_layer(
    const float* __restrict__ G, const float* __restrict__ whhL,
    const float* __restrict__ h0L, const float* __restrict__ c0L,
    __half* __restrict__ Yh)
{
    __shared__ __half hs[2][8][136];

    const int tid = threadIdx.x;
    const int w = tid >> 5, lane = tid & 31;
    const int d = blockIdx.y;
    const int b0 = blockIdx.x * 4;

    const float* wr = whhL + (size_t)d*G4*HH;
    unsigned wa[2][8][4];
#pragma unroll
    for (int mt = 0; mt < 2; mt++)
#pragma unroll
        for (int kt = 0; kt < 8; kt++)
#pragma unroll
            for (int r = 0; r < 4; r++){
                int grow = mt*16 + (lane>>2) + 8*(r & 1);
                int row = (grow >> 3)*128 + w*8 + (grow & 7);
                int k = kt*16 + (lane&3)*2 + 8*(r >> 1);
                wa[mt][kt][r] = h2u(wr[(size_t)row*HH + k], wr[(size_t)row*HH + k + 1]);
            }

    for (int i = tid; i < 2*8*136; i += 512) (&hs[0][0][0])[i] = __float2half(0.f);
    __syncthreads();

    const int q = lane >> 2, c = lane & 3;
    const int cell = w*8 + q;
    const size_t hb = (size_t)d*(BB*HH);
    float cv = c0L[hb + (size_t)(b0+c)*HH + cell];
    hs[0][2*c][cell] = __float2half(h0L[hb + (size_t)(b0+c)*HH + cell]);
    __syncthreads();

    const float* gbase = G + ((size_t)d*MM + b0 + c)*512 + cell;
    int tf = d ? (SS-1) : 0;
    float gp[4];
#pragma unroll
    for (int k = 0; k < 4; k++)
        gp[k] = gbase[(size_t)tf*BB*512 + 128*k];

    unsigned hsb0 = (unsigned)__cvta_generic_to_shared(&hs[0][0][0]);
    const unsigned boff = ((lane>>2)*136 + (lane&3)*2)*2;

    for (int s = 0; s < SS; s++){
        const int t = d ? (SS-1-s) : s;
        const int p = s & 1;
        unsigned hsb = hsb0 + (unsigned)(p * 8*136*2);

        float acc[2][4];
#pragma unroll
        for (int i=0;i<2;i++) for (int z=0;z<4;z++) acc[i][z]=0.f;
#pragma unroll
        for (int kt = 0; kt < 8; kt++){
            unsigned off = hsb + boff + kt*32;
            unsigned bf0, bf1;
            asm volatile("ld.shared.b32 %0, [%1];" : "=r"(bf0) : "r"(off));
            asm volatile("ld.shared.b32 %0, [%1];" : "=r"(bf1) : "r"(off + 16));
            mma16816(acc[0], wa[0][kt], bf0, bf1);
            mma16816(acc[1], wa[1][kt], bf0, bf1);
        }

        float gi = acc[0][0] + gp[0];
        float gf = acc[0][2] + gp[1];
        float gg = acc[1][0] + gp[2];
        float go = acc[1][2] + gp[3];

        if (s < SS-1){
            int tn = d ? (SS-2-s) : (s+1);
            size_t o = (size_t)tn*BB*512;
#pragma unroll
            for (int k = 0; k < 4; k++) gp[k] = gbase[o + 128*k];
        }

        float ig = sigf(gi), fg = sigf(gf);
        float g2 = tanha(gg), og = sigf(go);
        cv = fg*cv + ig*g2;
        float h = og * tanha(cv);

        hs[1-p][2*c][cell] = __float2half(h);
        Yh[((size_t)t*BB + b0 + c)*256 + d*128 + cell] = __float2half(h);
        __syncthreads();
    }
}

// ---- feats ----
__global__ __launch_bounds__(256) void feats_kernel(
    const __half* __restrict__ Y2, const float* __restrict__ wout,
    const float* __restrict__ bout, float* __restrict__ F)
{
    __shared__ float W[7][256];
    __shared__ float bo[7];
    const int tid = threadIdx.x;
    for (int i = tid; i < 7*256; i += 256) W[i>>8][i&255] = wout[i];
    if (tid < 7) bo[tid] = bout[tid];
    __syncthreads();
    const int warp = tid >> 5, lane = tid & 31;
    const size_t m = (size_t)blockIdx.x * 8 + warp;
    const __half* yr = Y2 + m * 256;
    float acc[7] = {0,0,0,0,0,0,0};
#pragma unroll
    for (int i = 0; i < 8; i++){
        int k = lane + 32*i;
        float x = __half2float(yr[k]);
#pragma unroll
        for (int t = 0; t < 7; t++) acc[t] += x * W[t][k];
    }
#pragma unroll
    for (int t = 0; t < 7; t++)
        for (int off = 16; off; off >>= 1)
            acc[t] += __shfl_down_sync(0xffffffffu, acc[t], off);
    if (lane == 0){
        int s = (int)(m >> 7), b = (int)(m & 127);
        float* fo = F + ((size_t)b*SS + s)*8;
#pragma unroll
        for (int t = 0; t < 7; t++) fo[t] = acc[t] + bo[t];
    }
}

// ---- Viterbi ----
__global__ __launch_bounds__(32) void viterbi_kernel(
    const float* __restrict__ F, const float* __restrict__ trans,
    float* __restrict__ out)
{
    __shared__ unsigned char bp[SS*8];
    const int b = blockIdx.x, lane = threadIdx.x;
    float tr[7];
#pragma unroll
    for (int p = 0; p < 7; p++) tr[p] = (lane < 7) ? trans[lane*7 + p] : 0.f;
    float fv = (lane == 5) ? 0.f : NEGV;
    const float* fb = F + (size_t)b*SS*8;
    for (int s = 0; s < SS; s++){
        float m = -3.4e38f; int arg = 0;
#pragma unroll
        for (int p = 0; p < 7; p++){
            float v = __shfl_sync(0xffffffffu, fv, p) + tr[p];
            if (v > m){ m = v; arg = p; }
        }
        if (lane < 7){
            fv = m + fb[s*8 + lane];
            bp[s*8 + lane] = (unsigned char)arg;
        }
    }
    __syncwarp();
    float term = fv + ((lane < 7) ? trans[6*7 + lane] : 0.f);
    if (lane >= 7) term = -3.4e38f;
    float bestv = -3.4e38f; int best = 0;
#pragma unroll
    for (int n = 0; n < 7; n++){
        float v = __shfl_sync(0xffffffffu, term, n);
        if (v > bestv){ bestv = v; best = n; }
    }
    if (lane == 0){
        out[(size_t)BB*SS + b] = bestv;
        float* po = out + (size_t)b*SS;
        int tag = best;
        for (int s = SS-1; s > 0; --s){ po[s] = (float)tag; tag = bp[s*8 + tag]; }
        po[0] = (float)tag;
    }
}

extern "C" void kernel_launch(void* const* d_in, const int* in_sizes, int n_in,
                              void* d_out, int out_size)
{
    const int*   sentence = (const int*)  d_in[0];
    const float* embed    = (const float*)d_in[1];
    const float* w_ih     = (const float*)d_in[2];
    const float* w_hh     = (const float*)d_in[3];
    const float* b_ih     = (const float*)d_in[4];
    const float* b_hh     = (const float*)d_in[5];
    const float* h0       = (const float*)d_in[6];
    const float* c0       = (const float*)d_in[7];
    const float* w_out    = (const float*)d_in[8];
    const float* b_out    = (const float*)d_in[9];
    const float* trans    = (const float*)d_in[10];
    float* out = (float*)d_out;

    float *G, *F, *BS;
    __half *Xh, *Y1h, *Y2h, *Wh;
    cudaGetSymbolAddress((void**)&G,   g_G);
    cudaGetSymbolAddress((void**)&F,   g_feats);
    cudaGetSymbolAddress((void**)&BS,  g_bs);
    cudaGetSymbolAddress((void**)&Xh,  g_xh);
    cudaGetSymbolAddress((void**)&Y1h, g_y1h);
    cudaGetSymbolAddress((void**)&Y2h, g_y2h);
    cudaGetSymbolAddress((void**)&Wh,  g_wh);

    const int gsmem = 2 * STAGEH * 2;
    cudaFuncSetAttribute(gemm16, cudaFuncAttributeMaxDynamicSharedMemorySize, gsmem);

    prep_x<<<MM*32/256, 256>>>(sentence, embed, Xh);
    prep_w<<<2048, 256>>>(w_ih, b_ih, b_hh, Wh, BS);

    dim3 ggrid(8, 1024);
    dim3 lgrid(32, 2);

    gemm16<<<ggrid, 256, gsmem>>>(Xh, Wh, BS, G);
    lstm_layer<<<lgrid, 512>>>(G, w_hh, h0, c0, Y1h);

    gemm16<<<ggrid, 256, gsmem>>>(Y1h, Wh + (size_t)1024*256, BS + 1024, G);
    lstm_layer<<<lgrid, 512>>>(G, w_hh + (size_t)1024*HH,
                               h0 + (size_t)2*BB*HH, c0 + (size_t)2*BB*HH, Y2h);

    feats_kernel<<<MM/8, 256>>>(Y2h, w_out, b_out, F);
    viterbi_kernel<<<BB, 32>>>(F, trans, out);
}

// round 14
// speedup vs baseline: 1.1634x; 1.0084x over previous
#include <cuda_runtime.h>
#include <cuda_fp16.h>
#include <cstdint>

#define EE 256
#define HH 128
#define G4 512
#define BB 128
#define SS 1024
#define MM (SS*BB)
#define NEGV -10000.0f

__device__ float  g_G[(size_t)2*MM*G4];
__device__ __half g_xh[(size_t)MM*256];
__device__ __half g_y1h[(size_t)MM*256];
__device__ __half g_y2h[(size_t)MM*256];
__device__ __half g_wh[(size_t)2*1024*256];
__device__ float  g_bs[2*1024];
__device__ float  g_feats[(size_t)BB*SS*8];

__device__ __forceinline__ unsigned h2u(float a, float b){
    __half2 h = __floats2half2_rn(a, b);
    return *(unsigned*)&h;
}
// fp16-accumulator HMMA
__device__ __forceinline__ void mma_h(unsigned* c, const unsigned* a,
                                      unsigned b0, unsigned b1){
    asm volatile("mma.sync.aligned.m16n8k16.row.col.f16.f16.f16.f16 "
        "{%0,%1}, {%2,%3,%4,%5}, {%6,%7}, {%0,%1};"
        : "+r"(c[0]), "+r"(c[1])
        : "r"(a[0]), "r"(a[1]), "r"(a[2]), "r"(a[3]), "r"(b0), "r"(b1));
}
__device__ __forceinline__ void ldm4(unsigned* r, unsigned addr){
    asm volatile("ldmatrix.sync.aligned.m8n8.x4.shared.b16 {%0,%1,%2,%3}, [%4];"
        : "=r"(r[0]), "=r"(r[1]), "=r"(r[2]), "=r"(r[3]) : "r"(addr));
}
__device__ __forceinline__ void cpa16(unsigned s, const void* g){
    asm volatile("cp.async.cg.shared.global [%0], [%1], 16;" :: "r"(s), "l"(g));
}
__device__ __forceinline__ float tanha(float x){
    float y; asm("tanh.approx.f32 %0, %1;" : "=f"(y) : "f"(x)); return y;
}
__device__ __forceinline__ float sigf(float x){
    return fmaf(0.5f, tanha(0.5f * x), 0.5f);
}

// ---- prep ----
__global__ __launch_bounds__(256) void prep_x(
    const int* __restrict__ sent, const float* __restrict__ emb,
    __half* __restrict__ Xh)
{
    size_t i = (size_t)blockIdx.x * 256 + threadIdx.x;
    int m = (int)(i >> 5);
    int c = ((int)i & 31) * 8;
    const float* src = emb + (size_t)sent[m]*256 + c;
    float4 v0 = *(const float4*)src;
    float4 v1 = *(const float4*)(src + 4);
    __half2* dst = (__half2*)(Xh + (size_t)m*256 + c);
    dst[0] = __floats2half2_rn(v0.x, v0.y);
    dst[1] = __floats2half2_rn(v0.z, v0.w);
    dst[2] = __floats2half2_rn(v1.x, v1.y);
    dst[3] = __floats2half2_rn(v1.z, v1.w);
}
__global__ __launch_bounds__(256) void prep_w(
    const float* __restrict__ wih, const float* __restrict__ bih,
    const float* __restrict__ bhh, __half* __restrict__ Wh, float* __restrict__ bs)
{
    size_t i = (size_t)blockIdx.x * 256 + threadIdx.x;
    Wh[i] = __float2half(wih[i]);
    if (i < 2048) bs[i] = bih[i] + bhh[i];
}

// ---- HMMA GEMM (fp16 accum), cp.async double-buffered, 2 blocks/SM ----
#define KC 64
#define ST2 72
#define XCH (128*ST2)
#define STAGEH (2*XCH)
__global__ __launch_bounds__(256, 2) void gemm16(
    const __half* __restrict__ Xh, const __half* __restrict__ Wh,
    const float* __restrict__ bs, float* __restrict__ G)
{
    extern __shared__ __half sm[];
    const int tid = threadIdx.x;
    const int n0 = blockIdx.x * 128;
    const int m0 = blockIdx.y * 128;

    unsigned sbase = (unsigned)__cvta_generic_to_shared(sm);
    const int lrow = tid >> 3, lc16 = tid & 7;

#define LOAD_STAGE(kc, stg) do{                                              \
        unsigned xb = sbase + (unsigned)(stg)*STAGEH*2;                      \
        unsigned wb = xb + XCH*2;                                            \
        _Pragma("unroll")                                                    \
        for (int it = 0; it < 4; it++){                                      \
            int row = lrow + 32*it;                                          \
            unsigned off = (unsigned)(row*ST2 + lc16*8)*2;                   \
            cpa16(xb + off, Xh + (size_t)(m0+row)*256 + (kc)*KC + lc16*8);   \
            cpa16(wb + off, Wh + (size_t)(n0+row)*256 + (kc)*KC + lc16*8);   \
        }                                                                    \
        asm volatile("cp.async.commit_group;");                              \
    }while(0)

    LOAD_STAGE(0, 0);
    LOAD_STAGE(1, 1);

    const int w = tid >> 5, lane = tid & 31;
    const int wm = (w >> 1) * 32, wn = (w & 1) * 64;
    unsigned acc[2][8][2];
#pragma unroll
    for (int i=0;i<2;i++) for (int j=0;j<8;j++){ acc[i][j][0]=0u; acc[i][j][1]=0u; }

#pragma unroll
    for (int ch = 0; ch < 4; ch++){
        if (ch < 3) asm volatile("cp.async.wait_group 1;");
        else        asm volatile("cp.async.wait_group 0;");
        __syncthreads();

        unsigned xb = sbase + (unsigned)(ch & 1)*STAGEH*2;
        unsigned wb = xb + XCH*2;
#pragma unroll
        for (int kt = 0; kt < 4; kt++){
            unsigned a[2][4], b[4][4];
#pragma unroll
            for (int mt = 0; mt < 2; mt++){
                int row = wm + mt*16 + (lane & 15);
                int k = kt*16 + (lane >> 4)*8;
                ldm4(a[mt], xb + (unsigned)(row*ST2 + k)*2);
            }
#pragma unroll
            for (int nh = 0; nh < 4; nh++){
                int row = wn + nh*16 + ((lane>>4)&1)*8 + (lane & 7);
                int k = kt*16 + ((lane>>3)&1)*8;
                ldm4(b[nh], wb + (unsigned)(row*ST2 + k)*2);
            }
#pragma unroll
            for (int mt = 0; mt < 2; mt++)
#pragma unroll
                for (int nh = 0; nh < 4; nh++){
                    mma_h(acc[mt][nh*2],   a[mt], b[nh][0], b[nh][1]);
                    mma_h(acc[mt][nh*2+1], a[mt], b[nh][2], b[nh][3]);
                }
        }
        __syncthreads();
        if (ch + 2 < 4) LOAD_STAGE(ch + 2, ch & 1);
    }

    const int d = n0 >> 9;
    const int t = m0 >> 7;
#pragma unroll
    for (int mt = 0; mt < 2; mt++){
#pragma unroll
        for (int nt = 0; nt < 8; nt++){
            int g = n0 + wn + nt*8 + (lane & 3)*2;
            float b0 = bs[g], b1 = bs[g+1];
            int gl = g & 511;
            int bA = (m0 + wm + mt*16 + (lane>>2)) & 127;
            size_t o = ((size_t)d*MM + (size_t)t*128)*512 + gl;
            float2 lo = __half22float2(*(__half2*)&acc[mt][nt][0]);
            float2 hi = __half22float2(*(__half2*)&acc[mt][nt][1]);
            *(float2*)(G + o + (size_t)bA*512) =
                make_float2(lo.x+b0, lo.y+b1);
            *(float2*)(G + o + (size_t)(bA+8)*512) =
                make_float2(hi.x+b0, hi.y+b1);
        }
    }
}

// ---- LSTM recurrence (R12 structure, fp16-accum mma) ----
__global__ __launch_bounds__(512, 1) void lstm_layer(
    const float* __restrict__ G, const float* __restrict__ whhL,
    const float* __restrict__ h0L, const float* __restrict__ c0L,
    __half* __restrict__ Yh)
{
    __shared__ __half hs[2][8][136];

    const int tid = threadIdx.x;
    const int w = tid >> 5, lane = tid & 31;
    const int d = blockIdx.y;
    const int b0 = blockIdx.x * 4;

    const float* wr = whhL + (size_t)d*G4*HH;
    unsigned wa[2][8][4];
#pragma unroll
    for (int mt = 0; mt < 2; mt++)
#pragma unroll
        for (int kt = 0; kt < 8; kt++)
#pragma unroll
            for (int r = 0; r < 4; r++){
                int grow = mt*16 + (lane>>2) + 8*(r & 1);
                int row = (grow >> 3)*128 + w*8 + (grow & 7);
                int k = kt*16 + (lane&3)*2 + 8*(r >> 1);
                wa[mt][kt][r] = h2u(wr[(size_t)row*HH + k], wr[(size_t)row*HH + k + 1]);
            }

    for (int i = tid; i < 2*8*136; i += 512) (&hs[0][0][0])[i] = __float2half(0.f);
    __syncthreads();

    const int q = lane >> 2, c = lane & 3;
    const int cell = w*8 + q;
    const size_t hb = (size_t)d*(BB*HH);
    float cv = c0L[hb + (size_t)(b0+c)*HH + cell];
    hs[0][2*c][cell] = __float2half(h0L[hb + (size_t)(b0+c)*HH + cell]);
    __syncthreads();

    const float* gbase = G + ((size_t)d*MM + b0 + c)*512 + cell;
    int tf = d ? (SS-1) : 0;
    float gp[4];
#pragma unroll
    for (int k = 0; k < 4; k++)
        gp[k] = gbase[(size_t)tf*BB*512 + 128*k];

    unsigned hsb0 = (unsigned)__cvta_generic_to_shared(&hs[0][0][0]);
    const unsigned boff = ((lane>>2)*136 + (lane&3)*2)*2;

    for (int s = 0; s < SS; s++){
        const int t = d ? (SS-1-s) : s;
        const int p = s & 1;
        unsigned hsb = hsb0 + (unsigned)(p * 8*136*2);

        unsigned acc[2][2];
        acc[0][0]=0u; acc[0][1]=0u; acc[1][0]=0u; acc[1][1]=0u;
#pragma unroll
        for (int kt = 0; kt < 8; kt++){
            unsigned off = hsb + boff + kt*32;
            unsigned bf0, bf1;
            asm volatile("ld.shared.b32 %0, [%1];" : "=r"(bf0) : "r"(off));
            asm volatile("ld.shared.b32 %0, [%1];" : "=r"(bf1) : "r"(off + 16));
            mma_h(acc[0], wa[0][kt], bf0, bf1);
            mma_h(acc[1], wa[1][kt], bf0, bf1);
        }

        // lane-local gates: low halves (col 2c): i=acc[0][0], f=acc[0][1],
        // g=acc[1][0], o=acc[1][1]
        float gi = __low2float(*(__half2*)&acc[0][0]) + gp[0];
        float gf = __low2float(*(__half2*)&acc[0][1]) + gp[1];
        float gg = __low2float(*(__half2*)&acc[1][0]) + gp[2];
        float go = __low2float(*(__half2*)&acc[1][1]) + gp[3];

        if (s < SS-1){
            int tn = d ? (SS-2-s) : (s+1);
            size_t o = (size_t)tn*BB*512;
#pragma unroll
            for (int k = 0; k < 4; k++) gp[k] = gbase[o + 128*k];
        }

        float ig = sigf(gi), fg = sigf(gf);
        float g2 = tanha(gg), og = sigf(go);
        cv = fg*cv + ig*g2;
        float h = og * tanha(cv);

        hs[1-p][2*c][cell] = __float2half(h);
        Yh[((size_t)t*BB + b0 + c)*256 + d*128 + cell] = __float2half(h);
        __syncthreads();
    }
}

// ---- feats ----
__global__ __launch_bounds__(256) void feats_kernel(
    const __half* __restrict__ Y2, const float* __restrict__ wout,
    const float* __restrict__ bout, float* __restrict__ F)
{
    __shared__ float W[7][256];
    __shared__ float bo[7];
    const int tid = threadIdx.x;
    for (int i = tid; i < 7*256; i += 256) W[i>>8][i&255] = wout[i];
    if (tid < 7) bo[tid] = bout[tid];
    __syncthreads();
    const int warp = tid >> 5, lane = tid & 31;
    const size_t m = (size_t)blockIdx.x * 8 + warp;
    const __half* yr = Y2 + m * 256;
    float acc[7] = {0,0,0,0,0,0,0};
#pragma unroll
    for (int i = 0; i < 8; i++){
        int k = lane + 32*i;
        float x = __half2float(yr[k]);
#pragma unroll
        for (int t = 0; t < 7; t++) acc[t] += x * W[t][k];
    }
#pragma unroll
    for (int t = 0; t < 7; t++)
        for (int off = 16; off; off >>= 1)
            acc[t] += __shfl_down_sync(0xffffffffu, acc[t], off);
    if (lane == 0){
        int s = (int)(m >> 7), b = (int)(m & 127);
        float* fo = F + ((size_t)b*SS + s)*8;
#pragma unroll
        for (int t = 0; t < 7; t++) fo[t] = acc[t] + bo[t];
    }
}

// ---- Viterbi ----
__global__ __launch_bounds__(32) void viterbi_kernel(
    const float* __restrict__ F, const float* __restrict__ trans,
    float* __restrict__ out)
{
    __shared__ unsigned char bp[SS*8];
    const int b = blockIdx.x, lane = threadIdx.x;
    float tr[7];
#pragma unroll
    for (int p = 0; p < 7; p++) tr[p] = (lane < 7) ? trans[lane*7 + p] : 0.f;
    float fv = (lane == 5) ? 0.f : NEGV;
    const float* fb = F + (size_t)b*SS*8;
    for (int s = 0; s < SS; s++){
        float m = -3.4e38f; int arg = 0;
#pragma unroll
        for (int p = 0; p < 7; p++){
            float v = __shfl_sync(0xffffffffu, fv, p) + tr[p];
            if (v > m){ m = v; arg = p; }
        }
        if (lane < 7){
            fv = m + fb[s*8 + lane];
            bp[s*8 + lane] = (unsigned char)arg;
        }
    }
    __syncwarp();
    float term = fv + ((lane < 7) ? trans[6*7 + lane] : 0.f);
    if (lane >= 7) term = -3.4e38f;
    float bestv = -3.4e38f; int best = 0;
#pragma unroll
    for (int n = 0; n < 7; n++){
        float v = __shfl_sync(0xffffffffu, term, n);
        if (v > bestv){ bestv = v; best = n; }
    }
    if (lane == 0){
        out[(size_t)BB*SS + b] = bestv;
        float* po = out + (size_t)b*SS;
        int tag = best;
        for (int s = SS-1; s > 0; --s){ po[s] = (float)tag; tag = bp[s*8 + tag]; }
        po[0] = (float)tag;
    }
}

extern "C" void kernel_launch(void* const* d_in, const int* in_sizes, int n_in,
                              void* d_out, int out_size)
{
    const int*   sentence = (const int*)  d_in[0];
    const float* embed    = (const float*)d_in[1];
    const float* w_ih     = (const float*)d_in[2];
    const float* w_hh     = (const float*)d_in[3];
    const float* b_ih     = (const float*)d_in[4];
    const float* b_hh     = (const float*)d_in[5];
    const float* h0       = (const float*)d_in[6];
    const float* c0       = (const float*)d_in[7];
    const float* w_out    = (const float*)d_in[8];
    const float* b_out    = (const float*)d_in[9];
    const float* trans    = (const float*)d_in[10];
    float* out = (float*)d_out;

    float *G, *F, *BS;
    __half *Xh, *Y1h, *Y2h, *Wh;
    cudaGetSymbolAddress((void**)&G,   g_G);
    cudaGetSymbolAddress((void**)&F,   g_feats);
    cudaGetSymbolAddress((void**)&BS,  g_bs);
    cudaGetSymbolAddress((void**)&Xh,  g_xh);
    cudaGetSymbolAddress((void**)&Y1h, g_y1h);
    cudaGetSymbolAddress((void**)&Y2h, g_y2h);
    cudaGetSymbolAddress((void**)&Wh,  g_wh);

    const int gsmem = 2 * STAGEH * 2;
    cudaFuncSetAttribute(gemm16, cudaFuncAttributeMaxDynamicSharedMemorySize, gsmem);

    prep_x<<<MM*32/256, 256>>>(sentence, embed, Xh);
    prep_w<<<2048, 256>>>(w_ih, b_ih, b_hh, Wh, BS);

    dim3 ggrid(8, 1024);
    dim3 lgrid(32, 2);

    gemm16<<<ggrid, 256, gsmem>>>(Xh, Wh, BS, G);
    lstm_layer<<<lgrid, 512>>>(G, w_hh, h0, c0, Y1h);

    gemm16<<<ggrid, 256, gsmem>>>(Y1h, Wh + (size_t)1024*256, BS + 1024, G);
    lstm_layer<<<lgrid, 512>>>(G, w_hh + (size_t)1024*HH,
                               h0 + (size_t)2*BB*HH, c0 + (size_t)2*BB*HH, Y2h);

    feats_kernel<<<MM/8, 256>>>(Y2h, w_out, b_out, F);
    viterbi_kernel<<<BB, 32>>>(F, trans, out);
}

// round 15
// speedup vs baseline: 1.1707x; 1.0063x over previous
#include <cuda_runtime.h>
#include <cuda_fp16.h>
#include <cstdint>

#define EE 256
#define HH 128
#define G4 512
#define BB 128
#define SS 1024
#define MM (SS*BB)
#define NEGV -10000.0f

__device__ float  g_G[(size_t)2*MM*G4];
__device__ __half g_xh[(size_t)MM*256];
__device__ __half g_y1h[(size_t)MM*256];
__device__ __half g_y2h[(size_t)MM*256];
__device__ __half g_wh[(size_t)2*1024*256];
__device__ float  g_bs[2*1024];
__device__ float  g_feats[(size_t)BB*SS*8];

__device__ __forceinline__ unsigned h2u(float a, float b){
    __half2 h = __floats2half2_rn(a, b);
    return *(unsigned*)&h;
}
// fp16-accumulator HMMA
__device__ __forceinline__ void mma_h(unsigned* c, const unsigned* a,
                                      unsigned b0, unsigned b1){
    asm volatile("mma.sync.aligned.m16n8k16.row.col.f16.f16.f16.f16 "
        "{%0,%1}, {%2,%3,%4,%5}, {%6,%7}, {%0,%1};"
        : "+r"(c[0]), "+r"(c[1])
        : "r"(a[0]), "r"(a[1]), "r"(a[2]), "r"(a[3]), "r"(b0), "r"(b1));
}
__device__ __forceinline__ void ldm4(unsigned* r, unsigned addr){
    asm volatile("ldmatrix.sync.aligned.m8n8.x4.shared.b16 {%0,%1,%2,%3}, [%4];"
        : "=r"(r[0]), "=r"(r[1]), "=r"(r[2]), "=r"(r[3]) : "r"(addr));
}
__device__ __forceinline__ void cpa16(unsigned s, const void* g){
    asm volatile("cp.async.cg.shared.global [%0], [%1], 16;" :: "r"(s), "l"(g));
}
__device__ __forceinline__ float tanha(float x){
    float y; asm("tanh.approx.f32 %0, %1;" : "=f"(y) : "f"(x)); return y;
}
__device__ __forceinline__ float sigf(float x){
    return fmaf(0.5f, tanha(0.5f * x), 0.5f);
}

// ---- prep ----
__global__ __launch_bounds__(256) void prep_x(
    const int* __restrict__ sent, const float* __restrict__ emb,
    __half* __restrict__ Xh)
{
    size_t i = (size_t)blockIdx.x * 256 + threadIdx.x;
    int m = (int)(i >> 5);
    int c = ((int)i & 31) * 8;
    const float* src = emb + (size_t)sent[m]*256 + c;
    float4 v0 = *(const float4*)src;
    float4 v1 = *(const float4*)(src + 4);
    __half2* dst = (__half2*)(Xh + (size_t)m*256 + c);
    dst[0] = __floats2half2_rn(v0.x, v0.y);
    dst[1] = __floats2half2_rn(v0.z, v0.w);
    dst[2] = __floats2half2_rn(v1.x, v1.y);
    dst[3] = __floats2half2_rn(v1.z, v1.w);
}
__global__ __launch_bounds__(256) void prep_w(
    const float* __restrict__ wih, const float* __restrict__ bih,
    const float* __restrict__ bhh, __half* __restrict__ Wh, float* __restrict__ bs)
{
    size_t i = (size_t)blockIdx.x * 256 + threadIdx.x;
    Wh[i] = __float2half(wih[i]);
    if (i < 2048) bs[i] = bih[i] + bhh[i];
}

// ---- HMMA GEMM (fp16 accum), cp.async 3-stage pipeline, 2 blocks/SM ----
#define KC 64
#define ST2 72
#define XCH (128*ST2)
#define STAGEH (2*XCH)
#define GSMEM (3*STAGEH*2)
__global__ __launch_bounds__(256, 2) void gemm16(
    const __half* __restrict__ Xh, const __half* __restrict__ Wh,
    const float* __restrict__ bs, float* __restrict__ G)
{
    extern __shared__ __half sm[];
    const int tid = threadIdx.x;
    const int n0 = blockIdx.x * 128;
    const int m0 = blockIdx.y * 128;

    unsigned sbase = (unsigned)__cvta_generic_to_shared(sm);
    const int lrow = tid >> 3, lc16 = tid & 7;

#define LOAD_STAGE(kc, stg) do{                                              \
        unsigned xb = sbase + (unsigned)(stg)*STAGEH*2;                      \
        unsigned wb = xb + XCH*2;                                            \
        _Pragma("unroll")                                                    \
        for (int it = 0; it < 4; it++){                                      \
            int row = lrow + 32*it;                                          \
            unsigned off = (unsigned)(row*ST2 + lc16*8)*2;                   \
            cpa16(xb + off, Xh + (size_t)(m0+row)*256 + (kc)*KC + lc16*8);   \
            cpa16(wb + off, Wh + (size_t)(n0+row)*256 + (kc)*KC + lc16*8);   \
        }                                                                    \
        asm volatile("cp.async.commit_group;");                              \
    }while(0)

    LOAD_STAGE(0, 0);
    LOAD_STAGE(1, 1);
    LOAD_STAGE(2, 2);

    const int w = tid >> 5, lane = tid & 31;
    const int wm = (w >> 1) * 32, wn = (w & 1) * 64;
    unsigned acc[2][8][2];
#pragma unroll
    for (int i=0;i<2;i++) for (int j=0;j<8;j++){ acc[i][j][0]=0u; acc[i][j][1]=0u; }

#pragma unroll
    for (int ch = 0; ch < 4; ch++){
        if (ch <= 1)      asm volatile("cp.async.wait_group 2;");
        else if (ch == 2) asm volatile("cp.async.wait_group 1;");
        else              asm volatile("cp.async.wait_group 0;");
        __syncthreads();

        unsigned xb = sbase + (unsigned)(ch % 3)*STAGEH*2;
        unsigned wb = xb + XCH*2;
#pragma unroll
        for (int kt = 0; kt < 4; kt++){
            unsigned a[2][4], b[4][4];
#pragma unroll
            for (int mt = 0; mt < 2; mt++){
                int row = wm + mt*16 + (lane & 15);
                int k = kt*16 + (lane >> 4)*8;
                ldm4(a[mt], xb + (unsigned)(row*ST2 + k)*2);
            }
#pragma unroll
            for (int nh = 0; nh < 4; nh++){
                int row = wn + nh*16 + ((lane>>4)&1)*8 + (lane & 7);
                int k = kt*16 + ((lane>>3)&1)*8;
                ldm4(b[nh], wb + (unsigned)(row*ST2 + k)*2);
            }
#pragma unroll
            for (int mt = 0; mt < 2; mt++)
#pragma unroll
                for (int nh = 0; nh < 4; nh++){
                    mma_h(acc[mt][nh*2],   a[mt], b[nh][0], b[nh][1]);
                    mma_h(acc[mt][nh*2+1], a[mt], b[nh][2], b[nh][3]);
                }
        }
        if (ch == 0){
            __syncthreads();           // stage 0 fully consumed
            LOAD_STAGE(3, 0);          // chunk 3 -> stage 0
        }
    }

    const int d = n0 >> 9;
    const int t = m0 >> 7;
#pragma unroll
    for (int mt = 0; mt < 2; mt++){
#pragma unroll
        for (int nt = 0; nt < 8; nt++){
            int g = n0 + wn + nt*8 + (lane & 3)*2;
            float b0 = bs[g], b1 = bs[g+1];
            int gl = g & 511;
            int bA = (m0 + wm + mt*16 + (lane>>2)) & 127;
            size_t o = ((size_t)d*MM + (size_t)t*128)*512 + gl;
            float2 lo = __half22float2(*(__half2*)&acc[mt][nt][0]);
            float2 hi = __half22float2(*(__half2*)&acc[mt][nt][1]);
            *(float2*)(G + o + (size_t)bA*512) =
                make_float2(lo.x+b0, lo.y+b1);
            *(float2*)(G + o + (size_t)(bA+8)*512) =
                make_float2(hi.x+b0, hi.y+b1);
        }
    }
}

// ---- LSTM recurrence (R14, unchanged) ----
__global__ __launch_bounds__(512, 1) void lstm_layer(
    const float* __restrict__ G, const float* __restrict__ whhL,
    const float* __restrict__ h0L, const float* __restrict__ c0L,
    __half* __restrict__ Yh)
{
    __shared__ __half hs[2][8][136];

    const int tid = threadIdx.x;
    const int w = tid >> 5, lane = tid & 31;
    const int d = blockIdx.y;
    const int b0 = blockIdx.x * 4;

    const float* wr = whhL + (size_t)d*G4*HH;
    unsigned wa[2][8][4];
#pragma unroll
    for (int mt = 0; mt < 2; mt++)
#pragma unroll
        for (int kt = 0; kt < 8; kt++)
#pragma unroll
            for (int r = 0; r < 4; r++){
                int grow = mt*16 + (lane>>2) + 8*(r & 1);
                int row = (grow >> 3)*128 + w*8 + (grow & 7);
                int k = kt*16 + (lane&3)*2 + 8*(r >> 1);
                wa[mt][kt][r] = h2u(wr[(size_t)row*HH + k], wr[(size_t)row*HH + k + 1]);
            }

    for (int i = tid; i < 2*8*136; i += 512) (&hs[0][0][0])[i] = __float2half(0.f);
    __syncthreads();

    const int q = lane >> 2, c = lane & 3;
    const int cell = w*8 + q;
    const size_t hb = (size_t)d*(BB*HH);
    float cv = c0L[hb + (size_t)(b0+c)*HH + cell];
    hs[0][2*c][cell] = __float2half(h0L[hb + (size_t)(b0+c)*HH + cell]);
    __syncthreads();

    const float* gbase = G + ((size_t)d*MM + b0 + c)*512 + cell;
    int tf = d ? (SS-1) : 0;
    float gp[4];
#pragma unroll
    for (int k = 0; k < 4; k++)
        gp[k] = gbase[(size_t)tf*BB*512 + 128*k];

    unsigned hsb0 = (unsigned)__cvta_generic_to_shared(&hs[0][0][0]);
    const unsigned boff = ((lane>>2)*136 + (lane&3)*2)*2;

    for (int s = 0; s < SS; s++){
        const int t = d ? (SS-1-s) : s;
        const int p = s & 1;
        unsigned hsb = hsb0 + (unsigned)(p * 8*136*2);

        unsigned acc[2][2];
        acc[0][0]=0u; acc[0][1]=0u; acc[1][0]=0u; acc[1][1]=0u;
#pragma unroll
        for (int kt = 0; kt < 8; kt++){
            unsigned off = hsb + boff + kt*32;
            unsigned bf0, bf1;
            asm volatile("ld.shared.b32 %0, [%1];" : "=r"(bf0) : "r"(off));
            asm volatile("ld.shared.b32 %0, [%1];" : "=r"(bf1) : "r"(off + 16));
            mma_h(acc[0], wa[0][kt], bf0, bf1);
            mma_h(acc[1], wa[1][kt], bf0, bf1);
        }

        float gi = __low2float(*(__half2*)&acc[0][0]) + gp[0];
        float gf = __low2float(*(__half2*)&acc[0][1]) + gp[1];
        float gg = __low2float(*(__half2*)&acc[1][0]) + gp[2];
        float go = __low2float(*(__half2*)&acc[1][1]) + gp[3];

        if (s < SS-1){
            int tn = d ? (SS-2-s) : (s+1);
            size_t o = (size_t)tn*BB*512;
#pragma unroll
            for (int k = 0; k < 4; k++) gp[k] = gbase[o + 128*k];
        }

        float ig = sigf(gi), fg = sigf(gf);
        float g2 = tanha(gg), og = sigf(go);
        cv = fg*cv + ig*g2;
        float h = og * tanha(cv);

        hs[1-p][2*c][cell] = __float2half(h);
        Yh[((size_t)t*BB + b0 + c)*256 + d*128 + cell] = __float2half(h);
        __syncthreads();
    }
}

// ---- feats ----
__global__ __launch_bounds__(256) void feats_kernel(
    const __half* __restrict__ Y2, const float* __restrict__ wout,
    const float* __restrict__ bout, float* __restrict__ F)
{
    __shared__ float W[7][256];
    __shared__ float bo[7];
    const int tid = threadIdx.x;
    for (int i = tid; i < 7*256; i += 256) W[i>>8][i&255] = wout[i];
    if (tid < 7) bo[tid] = bout[tid];
    __syncthreads();
    const int warp = tid >> 5, lane = tid & 31;
    const size_t m = (size_t)blockIdx.x * 8 + warp;
    const __half* yr = Y2 + m * 256;
    float acc[7] = {0,0,0,0,0,0,0};
#pragma unroll
    for (int i = 0; i < 8; i++){
        int k = lane + 32*i;
        float x = __half2float(yr[k]);
#pragma unroll
        for (int t = 0; t < 7; t++) acc[t] += x * W[t][k];
    }
#pragma unroll
    for (int t = 0; t < 7; t++)
        for (int off = 16; off; off >>= 1)
            acc[t] += __shfl_down_sync(0xffffffffu, acc[t], off);
    if (lane == 0){
        int s = (int)(m >> 7), b = (int)(m & 127);
        float* fo = F + ((size_t)b*SS + s)*8;
#pragma unroll
        for (int t = 0; t < 7; t++) fo[t] = acc[t] + bo[t];
    }
}

// ---- Viterbi ----
__global__ __launch_bounds__(32) void viterbi_kernel(
    const float* __restrict__ F, const float* __restrict__ trans,
    float* __restrict__ out)
{
    __shared__ unsigned char bp[SS*8];
    const int b = blockIdx.x, lane = threadIdx.x;
    float tr[7];
#pragma unroll
    for (int p = 0; p < 7; p++) tr[p] = (lane < 7) ? trans[lane*7 + p] : 0.f;
    float fv = (lane == 5) ? 0.f : NEGV;
    const float* fb = F + (size_t)b*SS*8;
    for (int s = 0; s < SS; s++){
        float m = -3.4e38f; int arg = 0;
#pragma unroll
        for (int p = 0; p < 7; p++){
            float v = __shfl_sync(0xffffffffu, fv, p) + tr[p];
            if (v > m){ m = v; arg = p; }
        }
        if (lane < 7){
            fv = m + fb[s*8 + lane];
            bp[s*8 + lane] = (unsigned char)arg;
        }
    }
    __syncwarp();
    float term = fv + ((lane < 7) ? trans[6*7 + lane] : 0.f);
    if (lane >= 7) term = -3.4e38f;
    float bestv = -3.4e38f; int best = 0;
#pragma unroll
    for (int n = 0; n < 7; n++){
        float v = __shfl_sync(0xffffffffu, term, n);
        if (v > bestv){ bestv = v; best = n; }
    }
    if (lane == 0){
        out[(size_t)BB*SS + b] = bestv;
        float* po = out + (size_t)b*SS;
        int tag = best;
        for (int s = SS-1; s > 0; --s){ po[s] = (float)tag; tag = bp[s*8 + tag]; }
        po[0] = (float)tag;
    }
}

extern "C" void kernel_launch(void* const* d_in, const int* in_sizes, int n_in,
                              void* d_out, int out_size)
{
    const int*   sentence = (const int*)  d_in[0];
    const float* embed    = (const float*)d_in[1];
    const float* w_ih     = (const float*)d_in[2];
    const float* w_hh     = (const float*)d_in[3];
    const float* b_ih     = (const float*)d_in[4];
    const float* b_hh     = (const float*)d_in[5];
    const float* h0       = (const float*)d_in[6];
    const float* c0       = (const float*)d_in[7];
    const float* w_out    = (const float*)d_in[8];
    const float* b_out    = (const float*)d_in[9];
    const float* trans    = (const float*)d_in[10];
    float* out = (float*)d_out;

    float *G, *F, *BS;
    __half *Xh, *Y1h, *Y2h, *Wh;
    cudaGetSymbolAddress((void**)&G,   g_G);
    cudaGetSymbolAddress((void**)&F,   g_feats);
    cudaGetSymbolAddress((void**)&BS,  g_bs);
    cudaGetSymbolAddress((void**)&Xh,  g_xh);
    cudaGetSymbolAddress((void**)&Y1h, g_y1h);
    cudaGetSymbolAddress((void**)&Y2h, g_y2h);
    cudaGetSymbolAddress((void**)&Wh,  g_wh);

    cudaFuncSetAttribute(gemm16, cudaFuncAttributeMaxDynamicSharedMemorySize, GSMEM);

    prep_x<<<MM*32/256, 256>>>(sentence, embed, Xh);
    prep_w<<<2048, 256>>>(w_ih, b_ih, b_hh, Wh, BS);

    dim3 ggrid(8, 1024);
    dim3 lgrid(32, 2);

    gemm16<<<ggrid, 256, GSMEM>>>(Xh, Wh, BS, G);
    lstm_layer<<<lgrid, 512>>>(G, w_hh, h0, c0, Y1h);

    gemm16<<<ggrid, 256, GSMEM>>>(Y1h, Wh + (size_t)1024*256, BS + 1024, G);
    lstm_layer<<<lgrid, 512>>>(G, w_hh + (size_t)1024*HH,
                               h0 + (size_t)2*BB*HH, c0 + (size_t)2*BB*HH, Y2h);

    feats_kernel<<<MM/8, 256>>>(Y2h, w_out, b_out, F);
    viterbi_kernel<<<BB, 32>>>(F, trans, out);
}